// round 1
// baseline (speedup 1.0000x reference)
#include <cuda_runtime.h>

#define KD 512
#define QD 256
#define N_ROWS 262144

#define MAIN_BLOCKS 444
#define MAIN_THREADS 256
#define WARPS_PER_BLOCK (MAIN_THREADS / 32)
#define NPART (MAIN_BLOCKS * WARPS_PER_BLOCK)           // 3552 warp partials
#define ROWS_PER_WARP ((N_ROWS + NPART - 1) / NPART)    // 74
#define RBLOCKS 74
#define PART_PER_RBLOCK (NPART / RBLOCKS)               // 48

// Scratch (static __device__ — no allocations allowed)
__device__ __align__(16) float g_q[KD];
__device__ float g_pm[NPART];
__device__ float g_pl[NPART];
__device__ __align__(16) float g_pacc[(size_t)NPART * KD];   // ~7.3 MB
__device__ float g_coef[NPART];
__device__ float g_L;
__device__ __align__(16) float g_red[RBLOCKS * KD];

__device__ __forceinline__ float neg_inf() { return __int_as_float(0xff800000); }

// ---------------- Kernel 1: q = W @ query + b  (512 outputs) ----------------
__global__ void qproj_kernel(const float* __restrict__ query,
                             const float* __restrict__ W,
                             const float* __restrict__ b) {
    __shared__ float sq[QD];
    for (int i = threadIdx.x; i < QD; i += blockDim.x) sq[i] = query[i];
    __syncthreads();
    const int wid = threadIdx.x >> 5;
    const int lid = threadIdx.x & 31;
    const int nw = blockDim.x >> 5;
    for (int row = wid; row < KD; row += nw) {
        float s = 0.f;
        #pragma unroll
        for (int j = lid; j < QD; j += 32) s += W[row * QD + j] * sq[j];
        #pragma unroll
        for (int o = 16; o > 0; o >>= 1) s += __shfl_xor_sync(0xffffffffu, s, o);
        if (lid == 0) g_q[row] = s + b[row];
    }
}

// ---------------- Kernel 2: fused online-softmax streaming pass ----------------
__global__ __launch_bounds__(MAIN_THREADS)
void attn_main(const float* __restrict__ key, const float* __restrict__ value) {
    const int lane = threadIdx.x & 31;
    const int warp = blockIdx.x * WARPS_PER_BLOCK + (threadIdx.x >> 5);

    // q held in registers: lane owns cols {4*lane..4*lane+3} + 3 more strided float4s
    const float4* q4 = reinterpret_cast<const float4*>(g_q);
    const float4 q0 = q4[lane], q1 = q4[lane + 32], q2 = q4[lane + 64], q3 = q4[lane + 96];

    float4 a0 = make_float4(0.f, 0.f, 0.f, 0.f), a1 = a0, a2 = a0, a3 = a0;
    float m = neg_inf();
    float l = 0.f;

    const float4* __restrict__ k4 = reinterpret_cast<const float4*>(key);
    const float4* __restrict__ v4 = reinterpret_cast<const float4*>(value);

    const int row_beg = warp * ROWS_PER_WARP;
    const int row_end = min(row_beg + ROWS_PER_WARP, N_ROWS);

    for (int row = row_beg; row < row_end; ++row) {
        const size_t base = (size_t)row * (KD / 4) + lane;
        // 8 independent LDG.128 per lane (4 KB per warp per row), fully coalesced
        const float4 k0 = k4[base], k1 = k4[base + 32], k2 = k4[base + 64], k3 = k4[base + 96];
        const float4 v0 = v4[base], v1 = v4[base + 32], v2 = v4[base + 64], v3 = v4[base + 96];

        float s;
        s  = k0.x * q0.x + k0.y * q0.y + k0.z * q0.z + k0.w * q0.w;
        s += k1.x * q1.x + k1.y * q1.y + k1.z * q1.z + k1.w * q1.w;
        s += k2.x * q2.x + k2.y * q2.y + k2.z * q2.z + k2.w * q2.w;
        s += k3.x * q3.x + k3.y * q3.y + k3.z * q3.z + k3.w * q3.w;
        #pragma unroll
        for (int o = 16; o > 0; o >>= 1) s += __shfl_xor_sync(0xffffffffu, s, o);

        // online softmax update
        const float mn = fmaxf(m, s);
        const float sc = __expf(m - mn);   // 0 on first iter (m = -inf)
        const float w  = __expf(s - mn);
        m = mn;
        l = l * sc + w;
        a0.x = a0.x * sc + w * v0.x;  a0.y = a0.y * sc + w * v0.y;
        a0.z = a0.z * sc + w * v0.z;  a0.w = a0.w * sc + w * v0.w;
        a1.x = a1.x * sc + w * v1.x;  a1.y = a1.y * sc + w * v1.y;
        a1.z = a1.z * sc + w * v1.z;  a1.w = a1.w * sc + w * v1.w;
        a2.x = a2.x * sc + w * v2.x;  a2.y = a2.y * sc + w * v2.y;
        a2.z = a2.z * sc + w * v2.z;  a2.w = a2.w * sc + w * v2.w;
        a3.x = a3.x * sc + w * v3.x;  a3.y = a3.y * sc + w * v3.y;
        a3.z = a3.z * sc + w * v3.z;  a3.w = a3.w * sc + w * v3.w;
    }

    float4* pa = reinterpret_cast<float4*>(g_pacc + (size_t)warp * KD);
    pa[lane] = a0; pa[lane + 32] = a1; pa[lane + 64] = a2; pa[lane + 96] = a3;
    if (lane == 0) { g_pm[warp] = m; g_pl[warp] = l; }
}

// ---------------- Kernel 3: global max, coefficients, L ----------------
__global__ void reduce_ml() {
    __shared__ float sdata[512];
    const int t = threadIdx.x;
    float mx = neg_inf();
    for (int i = t; i < NPART; i += 512) mx = fmaxf(mx, g_pm[i]);
    sdata[t] = mx;
    __syncthreads();
    for (int o = 256; o > 0; o >>= 1) {
        if (t < o) sdata[t] = fmaxf(sdata[t], sdata[t + o]);
        __syncthreads();
    }
    const float M = sdata[0];
    __syncthreads();
    float ls = 0.f;
    for (int i = t; i < NPART; i += 512) {
        const float c = __expf(g_pm[i] - M);
        g_coef[i] = c;
        ls += c * g_pl[i];
    }
    sdata[t] = ls;
    __syncthreads();
    for (int o = 256; o > 0; o >>= 1) {
        if (t < o) sdata[t] += sdata[t + o];
        __syncthreads();
    }
    if (t == 0) g_L = sdata[0];
}

// ---------------- Kernel 4: parallel weighted reduce of partial accumulators ----------------
__global__ void reduce_acc() {
    const int t = threadIdx.x;                 // 512 threads = one dim each
    const int b0 = blockIdx.x * PART_PER_RBLOCK;
    float acc = 0.f;
    #pragma unroll 4
    for (int b = b0; b < b0 + PART_PER_RBLOCK; ++b)
        acc += g_coef[b] * g_pacc[(size_t)b * KD + t];
    g_red[blockIdx.x * KD + t] = acc;
}

// ---------------- Kernel 5: finalize ----------------
__global__ void finalize_kernel(float* __restrict__ out) {
    const int t = threadIdx.x;
    float acc = 0.f;
    #pragma unroll 2
    for (int p = 0; p < RBLOCKS; ++p) acc += g_red[p * KD + t];
    out[t] = acc / g_L;
}

extern "C" void kernel_launch(void* const* d_in, const int* in_sizes, int n_in,
                              void* d_out, int out_size) {
    const float* query = (const float*)d_in[0];
    const float* key   = (const float*)d_in[1];
    const float* value = (const float*)d_in[2];
    const float* W     = (const float*)d_in[3];
    const float* b     = (const float*)d_in[4];
    float* out = (float*)d_out;

    qproj_kernel<<<1, 512>>>(query, W, b);
    attn_main<<<MAIN_BLOCKS, MAIN_THREADS>>>(key, value);
    reduce_ml<<<1, 512>>>();
    reduce_acc<<<RBLOCKS, KD>>>();
    finalize_kernel<<<1, KD>>>(out);
}

// round 3
// speedup vs baseline: 1.0732x; 1.0732x over previous
#include <cuda_runtime.h>

#define KD 512
#define QD 256
#define N_ROWS 262144

#define MAIN_BLOCKS 444
#define MAIN_THREADS 256
#define WARPS_PER_BLOCK (MAIN_THREADS / 32)
#define NWARPS_TOTAL (MAIN_BLOCKS * WARPS_PER_BLOCK)        // 3552 warps
#define NPART MAIN_BLOCKS                                   // 444 block partials
#define RBLOCKS 37
#define PART_PER_RBLOCK (NPART / RBLOCKS)                   // 12

// Scratch (static __device__ — no allocations allowed)
__device__ __align__(16) float g_q[KD];
__device__ float g_pm[NPART];
__device__ float g_pl[NPART];
__device__ __align__(16) float g_pacc[(size_t)NPART * KD];  // 0.91 MB
__device__ float g_coef[NPART];
__device__ float g_L;
__device__ __align__(16) float g_red[RBLOCKS * KD];

__device__ __forceinline__ float neg_inf() { return __int_as_float(0xff800000); }

// ---------------- Kernel 1: q = W @ query + b ----------------
__global__ void qproj_kernel(const float* __restrict__ query,
                             const float* __restrict__ W,
                             const float* __restrict__ b) {
    __shared__ float sq[QD];
    for (int i = threadIdx.x; i < QD; i += blockDim.x) sq[i] = query[i];
    __syncthreads();
    const int wid = threadIdx.x >> 5;
    const int lid = threadIdx.x & 31;
    const int nw = blockDim.x >> 5;
    for (int row = wid; row < KD; row += nw) {
        float s = 0.f;
        #pragma unroll
        for (int j = lid; j < QD; j += 32) s += W[row * QD + j] * sq[j];
        #pragma unroll
        for (int o = 16; o > 0; o >>= 1) s += __shfl_xor_sync(0xffffffffu, s, o);
        if (lid == 0) g_q[row] = s + b[row];
    }
}

// ---------------- Kernel 2: fused online-softmax streaming pass ----------------
__global__ __launch_bounds__(MAIN_THREADS)
void attn_main(const float* __restrict__ key, const float* __restrict__ value) {
    __shared__ float s_m[WARPS_PER_BLOCK];
    __shared__ float s_l[WARPS_PER_BLOCK];
    __shared__ __align__(16) float s_acc[WARPS_PER_BLOCK][KD];   // 16 KB

    const int lane = threadIdx.x & 31;
    const int wid  = threadIdx.x >> 5;
    const int warp = blockIdx.x * WARPS_PER_BLOCK + wid;

    const float4* q4 = reinterpret_cast<const float4*>(g_q);
    const float4 q0 = q4[lane], q1 = q4[lane + 32], q2 = q4[lane + 64], q3 = q4[lane + 96];

    const float4* __restrict__ k4 = reinterpret_cast<const float4*>(key);
    const float4* __restrict__ v4 = reinterpret_cast<const float4*>(value);

    // balanced partition: every warp gets 73 or 74 rows, none empty
    const int row_beg = (int)(((long long)warp * N_ROWS) / NWARPS_TOTAL);
    const int row_end = (int)(((long long)(warp + 1) * N_ROWS) / NWARPS_TOTAL);

    float4 a0 = make_float4(0.f, 0.f, 0.f, 0.f), a1 = a0, a2 = a0, a3 = a0;
    float m = neg_inf();
    float l = 0.f;

    for (int row = row_beg; row < row_end; ++row) {
        const size_t base = (size_t)row * (KD / 4) + lane;
        const float4 k0 = k4[base], k1 = k4[base + 32], k2 = k4[base + 64], k3 = k4[base + 96];
        const float4 v0 = v4[base], v1 = v4[base + 32], v2 = v4[base + 64], v3 = v4[base + 96];

        float s;
        s  = k0.x * q0.x + k0.y * q0.y + k0.z * q0.z + k0.w * q0.w;
        s += k1.x * q1.x + k1.y * q1.y + k1.z * q1.z + k1.w * q1.w;
        s += k2.x * q2.x + k2.y * q2.y + k2.z * q2.z + k2.w * q2.w;
        s += k3.x * q3.x + k3.y * q3.y + k3.z * q3.z + k3.w * q3.w;
        #pragma unroll
        for (int o = 16; o > 0; o >>= 1) s += __shfl_xor_sync(0xffffffffu, s, o);

        // warp-uniform branchy online softmax (s, m uniform across the warp)
        if (s > m) {
            // rescale path: new weight is exp(s-s)=1
            const float sc = (m == neg_inf()) ? 0.f : __expf(m - s);
            m = s;
            l = l * sc + 1.f;
            a0.x = a0.x * sc + v0.x;  a0.y = a0.y * sc + v0.y;
            a0.z = a0.z * sc + v0.z;  a0.w = a0.w * sc + v0.w;
            a1.x = a1.x * sc + v1.x;  a1.y = a1.y * sc + v1.y;
            a1.z = a1.z * sc + v1.z;  a1.w = a1.w * sc + v1.w;
            a2.x = a2.x * sc + v2.x;  a2.y = a2.y * sc + v2.y;
            a2.z = a2.z * sc + v2.z;  a2.w = a2.w * sc + v2.w;
            a3.x = a3.x * sc + v3.x;  a3.y = a3.y * sc + v3.y;
            a3.z = a3.z * sc + v3.z;  a3.w = a3.w * sc + v3.w;
        } else {
            // common path: no rescale
            const float w = __expf(s - m);
            l += w;
            a0.x += w * v0.x;  a0.y += w * v0.y;  a0.z += w * v0.z;  a0.w += w * v0.w;
            a1.x += w * v1.x;  a1.y += w * v1.y;  a1.z += w * v1.z;  a1.w += w * v1.w;
            a2.x += w * v2.x;  a2.y += w * v2.y;  a2.z += w * v2.z;  a2.w += w * v2.w;
            a3.x += w * v3.x;  a3.y += w * v3.y;  a3.z += w * v3.z;  a3.w += w * v3.w;
        }
    }

    // ---- block-level reduce of 8 warp partials (smem) ----
    float4* sa = reinterpret_cast<float4*>(s_acc[wid]);
    sa[lane] = a0; sa[lane + 32] = a1; sa[lane + 64] = a2; sa[lane + 96] = a3;
    if (lane == 0) { s_m[wid] = m; s_l[wid] = l; }
    __syncthreads();

    // every thread computes block max + per-warp coefficients (tiny, redundant)
    float Mb = neg_inf();
    #pragma unroll
    for (int w = 0; w < WARPS_PER_BLOCK; ++w) Mb = fmaxf(Mb, s_m[w]);
    float c[WARPS_PER_BLOCK];
    #pragma unroll
    for (int w = 0; w < WARPS_PER_BLOCK; ++w) c[w] = __expf(s_m[w] - Mb);

    // 256 threads x 2 dims each: weighted sum over 8 warps
    const int t = threadIdx.x;
    #pragma unroll
    for (int r = 0; r < 2; ++r) {
        const int d = t + r * MAIN_THREADS;
        float acc = 0.f;
        #pragma unroll
        for (int w = 0; w < WARPS_PER_BLOCK; ++w) acc += c[w] * s_acc[w][d];
        g_pacc[(size_t)blockIdx.x * KD + d] = acc;
    }
    if (t == 0) {
        float lb = 0.f;
        #pragma unroll
        for (int w = 0; w < WARPS_PER_BLOCK; ++w) lb += c[w] * s_l[w];
        g_pm[blockIdx.x] = Mb;
        g_pl[blockIdx.x] = lb;
    }
}

// ---------------- Kernel 3: global max, coefficients, L (444 entries) ----------------
__global__ void reduce_ml() {
    __shared__ float sdata[512];
    const int t = threadIdx.x;
    float mx = neg_inf();
    for (int i = t; i < NPART; i += 512) mx = fmaxf(mx, g_pm[i]);
    sdata[t] = mx;
    __syncthreads();
    for (int o = 256; o > 0; o >>= 1) {
        if (t < o) sdata[t] = fmaxf(sdata[t], sdata[t + o]);
        __syncthreads();
    }
    const float M = sdata[0];
    __syncthreads();
    float ls = 0.f;
    for (int i = t; i < NPART; i += 512) {
        const float cc = __expf(g_pm[i] - M);
        g_coef[i] = cc;
        ls += cc * g_pl[i];
    }
    sdata[t] = ls;
    __syncthreads();
    for (int o = 256; o > 0; o >>= 1) {
        if (t < o) sdata[t] += sdata[t + o];
        __syncthreads();
    }
    if (t == 0) g_L = sdata[0];
}

// ---------------- Kernel 4: parallel weighted reduce (37 blocks x 12 partials) ----------------
__global__ void reduce_acc() {
    const int t = threadIdx.x;                 // 512 threads, one dim each
    const int b0 = blockIdx.x * PART_PER_RBLOCK;
    float acc = 0.f;
    #pragma unroll
    for (int b = b0; b < b0 + PART_PER_RBLOCK; ++b)
        acc += g_coef[b] * g_pacc[(size_t)b * KD + t];
    g_red[blockIdx.x * KD + t] = acc;
}

// ---------------- Kernel 5: finalize ----------------
__global__ void finalize_kernel(float* __restrict__ out) {
    const int t = threadIdx.x;
    float acc = 0.f;
    #pragma unroll
    for (int p = 0; p < RBLOCKS; ++p) acc += g_red[p * KD + t];
    out[t] = acc / g_L;
}

extern "C" void kernel_launch(void* const* d_in, const int* in_sizes, int n_in,
                              void* d_out, int out_size) {
    const float* query = (const float*)d_in[0];
    const float* key   = (const float*)d_in[1];
    const float* value = (const float*)d_in[2];
    const float* W     = (const float*)d_in[3];
    const float* b     = (const float*)d_in[4];
    float* out = (float*)d_out;

    qproj_kernel<<<1, 512>>>(query, W, b);
    attn_main<<<MAIN_BLOCKS, MAIN_THREADS>>>(key, value);
    reduce_ml<<<1, 512>>>();
    reduce_acc<<<RBLOCKS, KD>>>();
    finalize_kernel<<<1, KD>>>(out);
}

// round 5
// speedup vs baseline: 1.2431x; 1.1583x over previous
#include <cuda_runtime.h>

#define KD 512
#define QD 256
#define N_ROWS 262144

#define MAIN_BLOCKS 444
#define MAIN_THREADS 256
#define WARPS_PER_BLOCK (MAIN_THREADS / 32)
#define CHUNK 16
#define NPART MAIN_BLOCKS                       // 444 block partials
#define RBLOCKS 37
#define PART_PER_RBLOCK (NPART / RBLOCKS)       // 12

// Scratch (static __device__ — no allocations allowed)
__device__ __align__(16) float g_q[KD];
__device__ float g_pm[NPART];
__device__ float g_pl[NPART];
__device__ __align__(16) float g_pacc[(size_t)NPART * KD];  // 0.91 MB
__device__ float g_coef[NPART];
__device__ float g_L;
__device__ __align__(16) float g_red[RBLOCKS * KD];
__device__ unsigned g_row_ctr;
__device__ unsigned g_done_a;
__device__ unsigned g_done_r;

__device__ __forceinline__ float neg_inf() { return __int_as_float(0xff800000); }

// safe exp(a - b): returns 0 when a == -inf (avoids -inf - -inf = NaN)
__device__ __forceinline__ float expw(float a, float b) {
    return (a == neg_inf()) ? 0.f : __expf(a - b);
}

// ---------------- Kernel 1: q = W @ query + b (64 blocks) + counter reset ----------------
__global__ void qproj_kernel(const float* __restrict__ query,
                             const float* __restrict__ W,
                             const float* __restrict__ b) {
    if (blockIdx.x == 0 && threadIdx.x == 0) {
        g_row_ctr = 0u; g_done_a = 0u; g_done_r = 0u;
    }
    __shared__ float sq[QD];
    sq[threadIdx.x] = query[threadIdx.x];
    __syncthreads();
    const int wid = threadIdx.x >> 5;
    const int lane = threadIdx.x & 31;
    const int row = blockIdx.x * WARPS_PER_BLOCK + wid;   // 64*8 = 512 rows
    const float4* w4 = reinterpret_cast<const float4*>(W + (size_t)row * QD);
    const float4 wa = w4[lane];
    const float4 wb = w4[lane + 32];
    const int c0 = 4 * lane;
    float s = wa.x * sq[c0] + wa.y * sq[c0 + 1] + wa.z * sq[c0 + 2] + wa.w * sq[c0 + 3]
            + wb.x * sq[128 + c0] + wb.y * sq[128 + c0 + 1]
            + wb.z * sq[128 + c0 + 2] + wb.w * sq[128 + c0 + 3];
    #pragma unroll
    for (int o = 16; o > 0; o >>= 1) s += __shfl_xor_sync(0xffffffffu, s, o);
    if (lane == 0) g_q[row] = s + b[row];
}

// ---------------- Kernel 2: fused streaming pass, dynamic chunks, fused ml-reduce ----------------
__global__ __launch_bounds__(MAIN_THREADS, 3)
void attn_main(const float* __restrict__ key, const float* __restrict__ value) {
    __shared__ float s_m[WARPS_PER_BLOCK];
    __shared__ float s_l[WARPS_PER_BLOCK];
    __shared__ __align__(16) float s_acc[WARPS_PER_BLOCK][KD];   // 16 KB
    __shared__ float s_red[MAIN_THREADS];
    __shared__ int s_last;

    const int lane = threadIdx.x & 31;
    const int wid  = threadIdx.x >> 5;
    const int tid  = threadIdx.x;

    const float4* q4 = reinterpret_cast<const float4*>(g_q);
    const float4 q0 = q4[lane], q1 = q4[lane + 32], q2 = q4[lane + 64], q3 = q4[lane + 96];

    const float4* __restrict__ k4 = reinterpret_cast<const float4*>(key);
    const float4* __restrict__ v4 = reinterpret_cast<const float4*>(value);

    float4 a0 = make_float4(0.f, 0.f, 0.f, 0.f), a1 = a0, a2 = a0, a3 = a0;
    float m = neg_inf();
    float l = 0.f;

    // dynamic chunk grabbing with one-chunk lookahead
    unsigned cur = 0u;
    if (lane == 0) cur = atomicAdd(&g_row_ctr, (unsigned)CHUNK);
    cur = __shfl_sync(0xffffffffu, cur, 0);

    while (cur < (unsigned)N_ROWS) {
        unsigned nxt = 0u;
        if (lane == 0) nxt = atomicAdd(&g_row_ctr, (unsigned)CHUNK);  // issued early, latency hidden
        nxt = __shfl_sync(0xffffffffu, nxt, 0);

        const unsigned row_end = min(cur + (unsigned)CHUNK, (unsigned)N_ROWS);
        for (unsigned row = cur; row < row_end; ++row) {
            const size_t base = (size_t)row * (KD / 4) + lane;
            const float4 k0 = __ldcs(&k4[base]);
            const float4 k1 = __ldcs(&k4[base + 32]);
            const float4 k2 = __ldcs(&k4[base + 64]);
            const float4 k3 = __ldcs(&k4[base + 96]);
            const float4 v0 = __ldcs(&v4[base]);
            const float4 v1 = __ldcs(&v4[base + 32]);
            const float4 v2 = __ldcs(&v4[base + 64]);
            const float4 v3 = __ldcs(&v4[base + 96]);

            float s;
            s  = k0.x * q0.x + k0.y * q0.y + k0.z * q0.z + k0.w * q0.w;
            s += k1.x * q1.x + k1.y * q1.y + k1.z * q1.z + k1.w * q1.w;
            s += k2.x * q2.x + k2.y * q2.y + k2.z * q2.z + k2.w * q2.w;
            s += k3.x * q3.x + k3.y * q3.y + k3.z * q3.z + k3.w * q3.w;
            #pragma unroll
            for (int o = 16; o > 0; o >>= 1) s += __shfl_xor_sync(0xffffffffu, s, o);

            if (s > m) {
                const float sc = (m == neg_inf()) ? 0.f : __expf(m - s);
                m = s;
                l = l * sc + 1.f;
                a0.x = a0.x * sc + v0.x;  a0.y = a0.y * sc + v0.y;
                a0.z = a0.z * sc + v0.z;  a0.w = a0.w * sc + v0.w;
                a1.x = a1.x * sc + v1.x;  a1.y = a1.y * sc + v1.y;
                a1.z = a1.z * sc + v1.z;  a1.w = a1.w * sc + v1.w;
                a2.x = a2.x * sc + v2.x;  a2.y = a2.y * sc + v2.y;
                a2.z = a2.z * sc + v2.z;  a2.w = a2.w * sc + v2.w;
                a3.x = a3.x * sc + v3.x;  a3.y = a3.y * sc + v3.y;
                a3.z = a3.z * sc + v3.z;  a3.w = a3.w * sc + v3.w;
            } else {
                const float w = __expf(s - m);
                l += w;
                a0.x += w * v0.x;  a0.y += w * v0.y;  a0.z += w * v0.z;  a0.w += w * v0.w;
                a1.x += w * v1.x;  a1.y += w * v1.y;  a1.z += w * v1.z;  a1.w += w * v1.w;
                a2.x += w * v2.x;  a2.y += w * v2.y;  a2.z += w * v2.z;  a2.w += w * v2.w;
                a3.x += w * v3.x;  a3.y += w * v3.y;  a3.z += w * v3.z;  a3.w += w * v3.w;
            }
        }
        cur = nxt;
    }

    // ---- block-level reduce of 8 warp partials ----
    float4* sa = reinterpret_cast<float4*>(s_acc[wid]);
    sa[lane] = a0; sa[lane + 32] = a1; sa[lane + 64] = a2; sa[lane + 96] = a3;
    if (lane == 0) { s_m[wid] = m; s_l[wid] = l; }
    __syncthreads();

    float Mb = neg_inf();
    #pragma unroll
    for (int w = 0; w < WARPS_PER_BLOCK; ++w) Mb = fmaxf(Mb, s_m[w]);
    float c[WARPS_PER_BLOCK];
    #pragma unroll
    for (int w = 0; w < WARPS_PER_BLOCK; ++w) c[w] = expw(s_m[w], Mb);

    #pragma unroll
    for (int r = 0; r < 2; ++r) {
        const int d = tid + r * MAIN_THREADS;
        float acc = 0.f;
        #pragma unroll
        for (int w = 0; w < WARPS_PER_BLOCK; ++w) acc += c[w] * s_acc[w][d];
        g_pacc[(size_t)blockIdx.x * KD + d] = acc;
    }
    if (tid == 0) {
        float lb = 0.f;
        #pragma unroll
        for (int w = 0; w < WARPS_PER_BLOCK; ++w) lb += c[w] * s_l[w];
        g_pm[blockIdx.x] = Mb;
        g_pl[blockIdx.x] = lb;
    }
    __syncthreads();

    // ---- last finishing block computes global max, coefs, L ----
    if (tid == 0) {
        __threadfence();
        const unsigned d = atomicAdd(&g_done_a, 1u);
        s_last = (d == MAIN_BLOCKS - 1u) ? 1 : 0;
    }
    __syncthreads();
    if (!s_last) return;

    float mx = neg_inf();
    for (int i = tid; i < NPART; i += MAIN_THREADS) mx = fmaxf(mx, __ldcg(&g_pm[i]));
    s_red[tid] = mx;
    __syncthreads();
    #pragma unroll
    for (int o = MAIN_THREADS / 2; o > 0; o >>= 1) {
        if (tid < o) s_red[tid] = fmaxf(s_red[tid], s_red[tid + o]);
        __syncthreads();
    }
    const float M = s_red[0];
    __syncthreads();

    float ls = 0.f;
    for (int i = tid; i < NPART; i += MAIN_THREADS) {
        const float pm = __ldcg(&g_pm[i]);
        const float cc = expw(pm, M);
        g_coef[i] = cc;
        ls += cc * __ldcg(&g_pl[i]);
    }
    s_red[tid] = ls;
    __syncthreads();
    #pragma unroll
    for (int o = MAIN_THREADS / 2; o > 0; o >>= 1) {
        if (tid < o) s_red[tid] += s_red[tid + o];
        __syncthreads();
    }
    if (tid == 0) g_L = s_red[0];
}

// ---------------- Kernel 3: weighted reduce + fused finalize ----------------
__global__ void reduce_out(float* __restrict__ out) {
    __shared__ int s_last;
    const int t = threadIdx.x;                 // 512 threads, one dim each
    const int b0 = blockIdx.x * PART_PER_RBLOCK;
    float acc = 0.f;
    #pragma unroll
    for (int b = b0; b < b0 + PART_PER_RBLOCK; ++b)
        acc += g_coef[b] * g_pacc[(size_t)b * KD + t];
    g_red[blockIdx.x * KD + t] = acc;
    __syncthreads();

    if (t == 0) {
        __threadfence();
        const unsigned d = atomicAdd(&g_done_r, 1u);
        s_last = (d == RBLOCKS - 1u) ? 1 : 0;
    }
    __syncthreads();
    if (!s_last) return;

    float a = 0.f;
    #pragma unroll
    for (int p = 0; p < RBLOCKS; ++p) a += __ldcg(&g_red[p * KD + t]);
    out[t] = a / g_L;
}

extern "C" void kernel_launch(void* const* d_in, const int* in_sizes, int n_in,
                              void* d_out, int out_size) {
    const float* query = (const float*)d_in[0];
    const float* key   = (const float*)d_in[1];
    const float* value = (const float*)d_in[2];
    const float* W     = (const float*)d_in[3];
    const float* b     = (const float*)d_in[4];
    float* out = (float*)d_out;

    qproj_kernel<<<64, QD>>>(query, W, b);
    attn_main<<<MAIN_BLOCKS, MAIN_THREADS>>>(key, value);
    reduce_out<<<RBLOCKS, KD>>>(out);
}